// round 15
// baseline (speedup 1.0000x reference)
#include <cuda_runtime.h>
#include <cuda_fp16.h>
#include <cstdint>

#define BB 16
#define SS 2048
#define HH 1024
#define DD 64
#define RR 2048
#define M_TOTAL (BB*SS)          // 32768 rows
#define NN 128                   // output cols (q | k)

#define BM 128
#define BN 128
#define BK 32                    // int8 k-elements per chunk = one k32 MMA step
#define BKP 48                   // padded row pitch in BYTES (32 + 16, 16B-aligned)
#define NKT (HH/BK)              // 32 k-chunks

// dynamic SMEM per buffer: A [128][48B] + B [128][48B]
#define A_TILE_B (BM*BKP)        // 6144
#define B_TILE_B (BN*BKP)        // 6144
#define BUF_B    (A_TILE_B + B_TILE_B)   // 12288
#define SMEM_DYN (2*BUF_B)       // 24576

// quantization scales
#define SA 21.16666667f          // 127/6
#define SW 508.0f                // 127/0.25
#define DEQ 9.29994419e-5f       // 1/(SA*SW)

// Scratch
__device__ __half  g_Q[M_TOTAL * DD];
__device__ __half  g_K[M_TOTAL * DD];
__device__ int8_t  g_Wq[NN * HH];    // W^T int8, [128 n][1024 k]

// ---------------- helpers ----------------
__device__ __forceinline__ uint32_t smem_u32(const void* p) {
    uint32_t a;
    asm("{ .reg .u64 t; cvta.to.shared.u64 t, %1; cvt.u32.u64 %0, t; }"
        : "=r"(a) : "l"(p));
    return a;
}
__device__ __forceinline__ int32_t q1(float x, float s) {
    return __float2int_rn(fminf(fmaxf(x * s, -127.f), 127.f));
}
__device__ __forceinline__ uint32_t qpack4(float4 v, float s) {
    int32_t i0 = q1(v.x, s), i1 = q1(v.y, s), i2 = q1(v.z, s), i3 = q1(v.w, s);
    return (uint32_t)(i0 & 255) | ((uint32_t)(i1 & 255) << 8) |
           ((uint32_t)(i2 & 255) << 16) | ((uint32_t)(i3 & 255) << 24);
}
__device__ __forceinline__ void sts128(uint32_t addr, uint32_t a, uint32_t b,
                                       uint32_t c, uint32_t d) {
    asm volatile("st.shared.v4.b32 [%0], {%1,%2,%3,%4};"
                 :: "r"(addr), "r"(a), "r"(b), "r"(c), "r"(d) : "memory");
}
__device__ __forceinline__ void ldsm4(uint32_t addr, uint32_t& r0, uint32_t& r1,
                                      uint32_t& r2, uint32_t& r3) {
    asm volatile("ldmatrix.sync.aligned.m8n8.x4.shared.b16 {%0,%1,%2,%3}, [%4];"
                 : "=r"(r0), "=r"(r1), "=r"(r2), "=r"(r3) : "r"(addr));
}
// int8 MMA m16n8k32, s32 accumulate
__device__ __forceinline__ void mma16832i(int32_t* c, uint32_t a0, uint32_t a1,
                                          uint32_t a2, uint32_t a3,
                                          uint32_t b0, uint32_t b1) {
    asm volatile(
        "mma.sync.aligned.m16n8k32.row.col.s32.s8.s8.s32 "
        "{%0,%1,%2,%3}, {%4,%5,%6,%7}, {%8,%9}, {%0,%1,%2,%3};"
        : "+r"(c[0]), "+r"(c[1]), "+r"(c[2]), "+r"(c[3])
        : "r"(a0), "r"(a1), "r"(a2), "r"(a3), "r"(b0), "r"(b1));
}

// ---------------------------------------------------------------------------
// Prep: W [1024][128] fp32 -> Wq [128][1024] int8 (transpose + quantize)
// ---------------------------------------------------------------------------
__global__ __launch_bounds__(256) void prep_w_kernel(const float* __restrict__ W) {
    __shared__ float t[32][33];
    const int k0 = blockIdx.x * 32;       // 32 tiles
    const int n0 = blockIdx.y * 32;       // 4 tiles
    const int r = threadIdx.x >> 5, c = threadIdx.x & 31;
#pragma unroll
    for (int i = 0; i < 4; ++i)
        t[r + 8 * i][c] = W[(size_t)(k0 + r + 8 * i) * NN + n0 + c];
    __syncthreads();
    // each thread packs 4 consecutive k bytes for one n
    const int nl = threadIdx.x >> 3;      // 0..31
    const int kq = threadIdx.x & 7;       // 0..7  -> k bytes kq*4..+3
    float4 v = make_float4(t[kq * 4 + 0][nl], t[kq * 4 + 1][nl],
                           t[kq * 4 + 2][nl], t[kq * 4 + 3][nl]);
    reinterpret_cast<uint32_t*>(g_Wq)[((size_t)(n0 + nl) * HH + k0) / 4 + kq] =
        qpack4(v, SW);
}

// ---------------------------------------------------------------------------
// GEMM via mma.sync int8 k32 / s32 acc, double-buffered, produce-before-compute.
// CTA: M=128, N=128, K=1024. 8 warps (2x4), warp tile 64x32. fp16 Q/K out.
// ---------------------------------------------------------------------------
__global__ __launch_bounds__(256, 2) void gemm_mma_kernel(
    const float* __restrict__ A,       // [M_TOTAL, 1024] fp32
    const float* __restrict__ bias,    // [128]
    const int*   __restrict__ pos_ids  // [M_TOTAL]
) {
    extern __shared__ char dsm[];
    const uint32_t sbase = smem_u32(dsm);

    const int tid  = threadIdx.x;
    const int lane = tid & 31;
    const int warp = tid >> 5;
    const int wm   = warp >> 2;       // 0..1
    const int wn   = warp & 3;        // 0..3
    const int blockM = blockIdx.x * BM;

    int32_t acc[4][4][4];
#pragma unroll
    for (int m = 0; m < 4; ++m)
#pragma unroll
        for (int n = 0; n < 4; ++n)
#pragma unroll
            for (int f = 0; f < 4; ++f) acc[m][n][f] = 0;

    // ---- load mappings: row = tid>>1 (0..127), kh = tid&1 (16-byte half) ----
    const int row = tid >> 1;
    const int kh  = tid & 1;
    const uint32_t a_sts = (uint32_t)(row * BKP + kh * 16);
    const uint32_t b_sts = (uint32_t)(A_TILE_B + row * BKP + kh * 16);

    // ldsm per-thread address pieces (bytes)
    const int a_lr   = lane & 7;
    const int a_tile = lane >> 3;
    const uint32_t a_addr_base =
        (uint32_t)((wm * 64 + (a_tile & 1) * 8 + a_lr) * BKP + (a_tile >> 1) * 16);
    const uint32_t b_addr_base =
        (uint32_t)(A_TILE_B + (wn * 32 + (a_tile & 1) * 8 + a_lr) * BKP +
                   (a_tile >> 1) * 16);

    float4 aldg[4];
    uint4  bldg;
    const float4* Ag = reinterpret_cast<const float4*>(A);
    const uint4*  Bg = reinterpret_cast<const uint4*>(g_Wq);

    // per-thread global offsets (float4 / uint4 units)
    const size_t a_g = (size_t)(blockM + row) * (HH / 4) + kh * 4;  // + kt*8 + i
    const size_t b_g = (size_t)row * (HH / 16) + kh;                // + kt*2

    // ---- prologue: chunk0 into buf0; prefetch chunk1 regs ----
    {
        const uint32_t buf = sbase;
#pragma unroll
        for (int i = 0; i < 4; ++i) aldg[i] = Ag[a_g + i];
        bldg = Bg[b_g];
        sts128(buf + a_sts, qpack4(aldg[0], SA), qpack4(aldg[1], SA),
                            qpack4(aldg[2], SA), qpack4(aldg[3], SA));
        sts128(buf + b_sts, bldg.x, bldg.y, bldg.z, bldg.w);
#pragma unroll
        for (int i = 0; i < 4; ++i) aldg[i] = Ag[a_g + 8 + i];
        bldg = Bg[b_g + 2];
        __syncthreads();
    }

    for (int kt = 0; kt < NKT; ++kt) {
        const uint32_t cur = sbase + (kt & 1) * BUF_B;
        const uint32_t nxt = sbase + ((kt + 1) & 1) * BUF_B;
        const bool more = (kt + 1 < NKT);

        // ---- produce chunk kt+1 into nxt from regs; prefetch kt+2 ----
        if (more) {
            sts128(nxt + a_sts, qpack4(aldg[0], SA), qpack4(aldg[1], SA),
                                qpack4(aldg[2], SA), qpack4(aldg[3], SA));
            sts128(nxt + b_sts, bldg.x, bldg.y, bldg.z, bldg.w);
            if (kt + 2 < NKT) {
#pragma unroll
                for (int i = 0; i < 4; ++i)
                    aldg[i] = Ag[a_g + (size_t)(kt + 2) * 8 + i];
                bldg = Bg[b_g + (size_t)(kt + 2) * 2];
            }
        }

        // ---- compute on cur: one k32 step ----
        {
            uint32_t bh[2][4];
#pragma unroll
            for (int n2 = 0; n2 < 2; ++n2) {
                uint32_t boff = cur + b_addr_base + (uint32_t)(n2 * 16 * BKP);
                ldsm4(boff, bh[n2][0], bh[n2][1], bh[n2][2], bh[n2][3]);
            }
#pragma unroll
            for (int m = 0; m < 4; ++m) {
                uint32_t aoff = cur + a_addr_base + (uint32_t)(m * 16 * BKP);
                uint32_t a0, a1, a2, a3;
                ldsm4(aoff, a0, a1, a2, a3);
#pragma unroll
                for (int n = 0; n < 4; ++n)
                    mma16832i(acc[m][n], a0, a1, a2, a3,
                              bh[n >> 1][n & 1], bh[n >> 1][(n & 1) + 2]);
            }
        }
        __syncthreads();
    }

    // ---- epilogue: dequant + bias + RoPE + fp16 split store ----
    const float LN1E4_OVER_32 = 0.28782313662425574f;   // ln(10000)/32
#pragma unroll
    for (int n = 0; n < 4; ++n) {
        const int col  = wn * 32 + n * 8 + (lane & 3) * 2;   // even
        const bool is_q = (col < DD);
        const int dloc  = col & (DD - 1);
        const float fr  = __expf(-(float)(dloc >> 1) * LN1E4_OVER_32);
        const float b0 = bias[col], b1 = bias[col + 1];
        __half* dst = is_q ? g_Q : g_K;
#pragma unroll
        for (int m = 0; m < 4; ++m) {
            const int ra = blockM + wm * 64 + m * 16 + (lane >> 2);
#pragma unroll
            for (int h = 0; h < 2; ++h) {
                const int r = ra + h * 8;
                const float pos = (float)__ldg(&pos_ids[r]);
                float s, c;
                __sincosf(pos * fr, &s, &c);
                const float x0 = (float)acc[m][n][2 * h]     * DEQ + b0;
                const float x1 = (float)acc[m][n][2 * h + 1] * DEQ + b1;
                __half2 y = __floats2half2_rn(x0 * c - x1 * s, x1 * c + x0 * s);
                *reinterpret_cast<__half2*>(&dst[(size_t)r * DD + dloc]) = y;
            }
        }
    }
}

// ---------------------------------------------------------------------------
// Relation gather + dot + mask. Four relations per warp, 8 lanes each.
// ---------------------------------------------------------------------------
__global__ __launch_bounds__(256) void relation_kernel(
    const int*   __restrict__ rel_idx,  // [B*R, 4]
    const float* __restrict__ mask,     // [B*R]
    float*       __restrict__ out       // [B*R]
) {
    const int warp = (blockIdx.x * blockDim.x + threadIdx.x) >> 5;
    const int lane = threadIdx.x & 31;
    const int sub  = lane >> 3;          // 0..3: relation within warp
    const int sl   = lane & 7;           // 16B slice within 128B row
    const int rel  = warp * 4 + sub;
    if (rel >= BB * RR) return;

    const int b    = rel / RR;
    const int4 idx = reinterpret_cast<const int4*>(rel_idx)[rel];
    const int base = b * SS;

    const uint4* Q4 = reinterpret_cast<const uint4*>(g_Q);
    const uint4* K4 = reinterpret_cast<const uint4*>(g_K);
    uint4 q0 = Q4[(size_t)(base + idx.x) * 8 + sl];
    uint4 q1 = Q4[(size_t)(base + idx.y) * 8 + sl];
    uint4 k2 = K4[(size_t)(base + idx.z) * 8 + sl];
    uint4 k3 = K4[(size_t)(base + idx.w) * 8 + sl];

    float sum = 0.0f;
    {
        const __half2* qa = reinterpret_cast<const __half2*>(&q0);
        const __half2* ka = reinterpret_cast<const __half2*>(&k2);
        const __half2* qb = reinterpret_cast<const __half2*>(&q1);
        const __half2* kb = reinterpret_cast<const __half2*>(&k3);
#pragma unroll
        for (int j = 0; j < 4; ++j) {
            float2 x = __half22float2(qa[j]), y = __half22float2(ka[j]);
            sum += x.x * y.x + x.y * y.y;
            x = __half22float2(qb[j]); y = __half22float2(kb[j]);
            sum += x.x * y.x + x.y * y.y;
        }
    }
#pragma unroll
    for (int off = 4; off > 0; off >>= 1)
        sum += __shfl_xor_sync(0xffffffffu, sum, off);

    if (sl == 0) {
        const float m = mask[rel];
        out[rel] = (sum + (1.0f - m) * -1e12f) * 0.125f;  // 1/sqrt(64)
    }
}

extern "C" void kernel_launch(void* const* d_in, const int* in_sizes, int n_in,
                              void* d_out, int out_size) {
    const float* lhs  = (const float*)d_in[0];   // [B,S,H]
    const float* W    = (const float*)d_in[1];   // [H,128]
    const float* bias = (const float*)d_in[2];   // [128]
    const int*   pos  = (const int*)d_in[3];     // [B,S]
    const int*   ridx = (const int*)d_in[4];     // [B,R,4]
    const float* lm   = (const float*)d_in[5];   // [B,R]
    float* out = (float*)d_out;                  // [B,R]

    static bool attr_set = false;
    if (!attr_set) {
        cudaFuncSetAttribute(gemm_mma_kernel,
                             cudaFuncAttributeMaxDynamicSharedMemorySize, SMEM_DYN);
        attr_set = true;
    }
    prep_w_kernel<<<dim3(32, 4), 256>>>(W);
    gemm_mma_kernel<<<M_TOTAL / BM, 256, SMEM_DYN>>>(lhs, bias, pos);
    relation_kernel<<<(BB * RR / 4 + 7) / 8, 256>>>(ridx, lm, out);
}

// round 16
// speedup vs baseline: 1.9528x; 1.9528x over previous
#include <cuda_runtime.h>
#include <cuda_fp16.h>
#include <cstdint>

#define BB 16
#define SS 2048
#define HH 1024
#define DD 64
#define RR 2048
#define M_TOTAL (BB*SS)          // 32768 rows
#define NN 128                   // output cols (q | k)

#define BM 128
#define BN 128
#define BK 32
#define BKP 40                   // A tile padded row length in fp16 (80B rows)
#define BNP 136                  // B tile padded row length in fp16 (272B = 17x16B, odd)
#define NKT (HH/BK)              // 32 k-chunks

// dynamic SMEM per buffer: A [128][40] fp16 = 10240 B, B [32][136] fp16 = 8704 B
#define A_TILE_B (BM*BKP*2)      // 10240
#define B_TILE_B (BK*BNP*2)      // 8704
#define BUF_B    (A_TILE_B + B_TILE_B)   // 18944
#define SMEM_DYN (2*BUF_B)       // 37888

// Scratch: Q/K in fp16
__device__ __half g_Q[M_TOTAL * DD];
__device__ __half g_K[M_TOTAL * DD];

// ---------------- helpers ----------------
__device__ __forceinline__ uint32_t smem_u32(const void* p) {
    uint32_t a;
    asm("{ .reg .u64 t; cvta.to.shared.u64 t, %1; cvt.u32.u64 %0, t; }"
        : "=r"(a) : "l"(p));
    return a;
}
// pack f16(lo),f16(hi): first PTX source lands in HIGH half
__device__ __forceinline__ uint32_t f2h2(float lo, float hi) {
    uint32_t r;
    asm("cvt.rn.f16x2.f32 %0, %1, %2;" : "=r"(r) : "f"(hi), "f"(lo));
    return r;
}
__device__ __forceinline__ void sts64(uint32_t addr, uint32_t a, uint32_t b) {
    asm volatile("st.shared.v2.b32 [%0], {%1,%2};" :: "r"(addr), "r"(a), "r"(b) : "memory");
}
__device__ __forceinline__ void ldsm4(uint32_t addr, uint32_t& r0, uint32_t& r1,
                                      uint32_t& r2, uint32_t& r3) {
    asm volatile("ldmatrix.sync.aligned.m8n8.x4.shared.b16 {%0,%1,%2,%3}, [%4];"
                 : "=r"(r0), "=r"(r1), "=r"(r2), "=r"(r3) : "r"(addr));
}
__device__ __forceinline__ void ldsm4t(uint32_t addr, uint32_t& r0, uint32_t& r1,
                                       uint32_t& r2, uint32_t& r3) {
    asm volatile("ldmatrix.sync.aligned.m8n8.x4.trans.shared.b16 {%0,%1,%2,%3}, [%4];"
                 : "=r"(r0), "=r"(r1), "=r"(r2), "=r"(r3) : "r"(addr));
}
// fp16-accumulate MMA: C/D are 2 packed f16x2 regs
__device__ __forceinline__ void mma16816h(uint32_t* c, uint32_t a0, uint32_t a1,
                                          uint32_t a2, uint32_t a3,
                                          uint32_t b0, uint32_t b1) {
    asm volatile(
        "mma.sync.aligned.m16n8k16.row.col.f16.f16.f16.f16 "
        "{%0,%1}, {%2,%3,%4,%5}, {%6,%7}, {%0,%1};"
        : "+r"(c[0]), "+r"(c[1])
        : "r"(a0), "r"(a1), "r"(a2), "r"(a3), "r"(b0), "r"(b1));
}

// ---------------------------------------------------------------------------
// GEMM via mma.sync fp16 in/acc, double-buffered, produce-before-compute.
// A and B both register-prefetched one chunk ahead; B converted from fp32 W
// [k][n] in-kernel (no prep kernel), consumed via trans-ldsm.
// CTA: M=128, N=128, K=1024. 8 warps (2x4), warp tile 64x32. fp16 Q/K out.
// ---------------------------------------------------------------------------
__global__ __launch_bounds__(256, 2) void gemm_mma_kernel(
    const float* __restrict__ A,       // [M_TOTAL, 1024]
    const float* __restrict__ W,       // [1024, 128] fp32
    const float* __restrict__ bias,    // [128]
    const int*   __restrict__ pos_ids  // [M_TOTAL]
) {
    extern __shared__ char dsm[];
    const uint32_t sbase = smem_u32(dsm);

    const int tid  = threadIdx.x;
    const int lane = tid & 31;
    const int warp = tid >> 5;
    const int wm   = warp >> 2;       // 0..1
    const int wn   = warp & 3;        // 0..3
    const int blockM = blockIdx.x * BM;

    uint32_t acc[4][4][2];
#pragma unroll
    for (int m = 0; m < 4; ++m)
#pragma unroll
        for (int n = 0; n < 4; ++n) { acc[m][n][0] = 0u; acc[m][n][1] = 0u; }

    // ---- load mappings ----
    const int arow0 = tid >> 3;       // 0..31 (A rows arow0 + 32*i)
    const int af    = tid & 7;        // float4 index within 32-float k-chunk

    const int brow0 = tid >> 5;       // B k-row for j=0 (then +8 per j)
    const int bcol4 = tid & 31;
    const uint32_t b_sts_base =
        (uint32_t)(A_TILE_B + (brow0 * BNP + bcol4 * 4) * 2);

    // ldmatrix per-thread address pieces
    const int a_lr   = lane & 7;
    const int a_tile = lane >> 3;
    const uint32_t a_addr_base =
        (uint32_t)(((wm * 64 + (a_tile & 1) * 8 + a_lr) * BKP + (a_tile >> 1) * 8) * 2);
    // trans-ldsm B: [k][n] layout
    const uint32_t b_addr_base =
        (uint32_t)(((lane & 15) * BNP + wn * 32 + (lane >> 4) * 8) * 2);

    float4 aldg[4], bldg[4];
    const float4* Ag = reinterpret_cast<const float4*>(A);
    const float4* Wg = reinterpret_cast<const float4*>(W);

    // ---- prologue ----
    // invariant at iter kt: cur holds chunk kt; aldg/bldg hold chunk kt+1.
    {
        const uint32_t buf = sbase;
#pragma unroll
        for (int i = 0; i < 4; ++i)
            aldg[i] = Ag[((size_t)(blockM + arow0 + 32 * i) * HH) / 4 + af];
#pragma unroll
        for (int j = 0; j < 4; ++j)
            bldg[j] = Wg[j * 256 + tid];
#pragma unroll
        for (int i = 0; i < 4; ++i) {
            uint32_t p0 = f2h2(aldg[i].x, aldg[i].y);
            uint32_t p1 = f2h2(aldg[i].z, aldg[i].w);
            sts64(buf + (uint32_t)(((arow0 + 32 * i) * BKP + af * 4) * 2), p0, p1);
        }
#pragma unroll
        for (int j = 0; j < 4; ++j)
            sts64(buf + b_sts_base + (uint32_t)(j * 8 * BNP * 2),
                  f2h2(bldg[j].x, bldg[j].y), f2h2(bldg[j].z, bldg[j].w));
#pragma unroll
        for (int i = 0; i < 4; ++i)
            aldg[i] = Ag[((size_t)(blockM + arow0 + 32 * i) * HH + BK) / 4 + af];
#pragma unroll
        for (int j = 0; j < 4; ++j)
            bldg[j] = Wg[BK * 32 + j * 256 + tid];
        __syncthreads();
    }

    for (int kt = 0; kt < NKT; ++kt) {
        const uint32_t cur = sbase + (kt & 1) * BUF_B;
        const uint32_t nxt = sbase + ((kt + 1) & 1) * BUF_B;
        const bool more = (kt + 1 < NKT);

        // ---- produce chunk kt+1 into nxt from regs; prefetch kt+2 ----
        if (more) {
#pragma unroll
            for (int i = 0; i < 4; ++i) {
                uint32_t p0 = f2h2(aldg[i].x, aldg[i].y);
                uint32_t p1 = f2h2(aldg[i].z, aldg[i].w);
                sts64(nxt + (uint32_t)(((arow0 + 32 * i) * BKP + af * 4) * 2), p0, p1);
            }
#pragma unroll
            for (int j = 0; j < 4; ++j)
                sts64(nxt + b_sts_base + (uint32_t)(j * 8 * BNP * 2),
                      f2h2(bldg[j].x, bldg[j].y), f2h2(bldg[j].z, bldg[j].w));
            if (kt + 2 < NKT) {
                const int kn = (kt + 2) * BK;
#pragma unroll
                for (int i = 0; i < 4; ++i)
                    aldg[i] = Ag[((size_t)(blockM + arow0 + 32 * i) * HH + kn) / 4 + af];
#pragma unroll
                for (int j = 0; j < 4; ++j)
                    bldg[j] = Wg[kn * 32 + j * 256 + tid];
            }
        }

        // ---- compute on cur: 2 k16 steps ----
        const uint32_t sA = cur, sB = cur + A_TILE_B;
#pragma unroll
        for (int kk = 0; kk < BK; kk += 16) {
            uint32_t bh[2][4];
#pragma unroll
            for (int n2 = 0; n2 < 2; ++n2) {
                uint32_t boff = b_addr_base + (uint32_t)((kk * BNP + n2 * 16) * 2);
                ldsm4t(sB + boff, bh[n2][0], bh[n2][1], bh[n2][2], bh[n2][3]);
            }
#pragma unroll
            for (int m = 0; m < 4; ++m) {
                uint32_t aoff = a_addr_base + (uint32_t)((m * 16 * BKP + kk) * 2);
                uint32_t a0, a1, a2, a3;
                ldsm4(sA + aoff, a0, a1, a2, a3);
#pragma unroll
                for (int n = 0; n < 4; ++n)
                    mma16816h(acc[m][n], a0, a1, a2, a3,
                              bh[n >> 1][(n & 1) * 2], bh[n >> 1][(n & 1) * 2 + 1]);
            }
        }
        __syncthreads();
    }

    // ---- epilogue: bias + RoPE + fp16 split store ----
    const float LN1E4_OVER_32 = 0.28782313662425574f;   // ln(10000)/32
#pragma unroll
    for (int n = 0; n < 4; ++n) {
        const int col  = wn * 32 + n * 8 + (lane & 3) * 2;   // even
        const bool is_q = (col < DD);
        const int dloc  = col & (DD - 1);
        const float fr  = __expf(-(float)(dloc >> 1) * LN1E4_OVER_32);
        const float b0 = bias[col], b1 = bias[col + 1];
        __half* dst = is_q ? g_Q : g_K;
#pragma unroll
        for (int m = 0; m < 4; ++m) {
            const int ra = blockM + wm * 64 + m * 16 + (lane >> 2);
#pragma unroll
            for (int h = 0; h < 2; ++h) {
                const int r = ra + h * 8;
                const float pos = (float)__ldg(&pos_ids[r]);
                float s, c;
                __sincosf(pos * fr, &s, &c);
                float2 xv = __half22float2(
                    *reinterpret_cast<const __half2*>(&acc[m][n][h]));
                const float x0 = xv.x + b0;
                const float x1 = xv.y + b1;
                __half2 y = __floats2half2_rn(x0 * c - x1 * s, x1 * c + x0 * s);
                *reinterpret_cast<__half2*>(&dst[(size_t)r * DD + dloc]) = y;
            }
        }
    }
}

// ---------------------------------------------------------------------------
// Relation gather + dot + mask. Eight relations per warp, 4 lanes each,
// 8 independent LDG.128 per lane (two slices of each of q0/q1/k2/k3): MLP=8.
// ---------------------------------------------------------------------------
__global__ __launch_bounds__(256) void relation_kernel(
    const int*   __restrict__ rel_idx,  // [B*R, 4]
    const float* __restrict__ mask,     // [B*R]
    float*       __restrict__ out       // [B*R]
) {
    const int warp = (blockIdx.x * blockDim.x + threadIdx.x) >> 5;
    const int lane = threadIdx.x & 31;
    const int sub  = lane >> 2;          // 0..7: relation within warp
    const int sl   = lane & 3;           // 16B slice pair selector
    const int rel  = warp * 8 + sub;
    if (rel >= BB * RR) return;

    const int b    = rel / RR;
    const int4 idx = reinterpret_cast<const int4*>(rel_idx)[rel];
    const int base = b * SS;

    const uint4* Q4 = reinterpret_cast<const uint4*>(g_Q);
    const uint4* K4 = reinterpret_cast<const uint4*>(g_K);
    const size_t r0 = (size_t)(base + idx.x) * 8;
    const size_t r1 = (size_t)(base + idx.y) * 8;
    const size_t r2 = (size_t)(base + idx.z) * 8;
    const size_t r3 = (size_t)(base + idx.w) * 8;

    // 8 independent loads (slices sl and sl+4 of each 8-slice row)
    uint4 q0a = Q4[r0 + sl],     q1a = Q4[r1 + sl];
    uint4 k2a = K4[r2 + sl],     k3a = K4[r3 + sl];
    uint4 q0b = Q4[r0 + sl + 4], q1b = Q4[r1 + sl + 4];
    uint4 k2b = K4[r2 + sl + 4], k3b = K4[r3 + sl + 4];

    float sum = 0.0f;
    {
        const __half2* pq; const __half2* pk;
#define DOT4(QV, KV) \
        pq = reinterpret_cast<const __half2*>(&(QV)); \
        pk = reinterpret_cast<const __half2*>(&(KV)); \
        _Pragma("unroll") \
        for (int j = 0; j < 4; ++j) { \
            float2 x = __half22float2(pq[j]); \
            float2 y = __half22float2(pk[j]); \
            sum += x.x * y.x + x.y * y.y; \
        }
        DOT4(q0a, k2a) DOT4(q0b, k2b) DOT4(q1a, k3a) DOT4(q1b, k3b)
#undef DOT4
    }
    sum += __shfl_xor_sync(0xffffffffu, sum, 1);
    sum += __shfl_xor_sync(0xffffffffu, sum, 2);

    if (sl == 0) {
        const float m = mask[rel];
        out[rel] = (sum + (1.0f - m) * -1e12f) * 0.125f;  // 1/sqrt(64)
    }
}

extern "C" void kernel_launch(void* const* d_in, const int* in_sizes, int n_in,
                              void* d_out, int out_size) {
    const float* lhs  = (const float*)d_in[0];   // [B,S,H]
    const float* W    = (const float*)d_in[1];   // [H,128]
    const float* bias = (const float*)d_in[2];   // [128]
    const int*   pos  = (const int*)d_in[3];     // [B,S]
    const int*   ridx = (const int*)d_in[4];     // [B,R,4]
    const float* lm   = (const float*)d_in[5];   // [B,R]
    float* out = (float*)d_out;                  // [B,R]

    static bool attr_set = false;
    if (!attr_set) {
        cudaFuncSetAttribute(gemm_mma_kernel,
                             cudaFuncAttributeMaxDynamicSharedMemorySize, SMEM_DYN);
        attr_set = true;
    }
    gemm_mma_kernel<<<M_TOTAL / BM, 256, SMEM_DYN>>>(lhs, W, bias, pos);
    relation_kernel<<<(BB * RR / 8 + 7) / 8, 256>>>(ridx, lm, out);
}